// round 1
// baseline (speedup 1.0000x reference)
#include <cuda_runtime.h>
#include <math.h>
#include <stdint.h>

// ---------------------------------------------------------------------------
// Problem constants
//   S=4096, D_IN=1024, E=512, OUT=256, HEAD_DIM=2
// Key pruning: final output = softmax(row 4095 of post-attn MLP), which
// depends only on attn_out[3584+j, 511]  (j = 0..511)
//   => need: full encoder (h for all S rows), k (all rows), q rows 3584:4096,
//      v column 511, softmax rows 3584:4096 of both heads, suffix-sum of vcol.
// ---------------------------------------------------------------------------

// Scratch (static device allocations; no cudaMalloc anywhere)
__device__ float g_A[4096 * 2048];   // h1, then h3
__device__ float g_B[4096 * 4096];   // h2
__device__ float g_h[4096 * 512];    // encoder output + positional encoding
__device__ float g_k[4096 * 512];    // k = qkv[:,512:1024]
__device__ float g_q[512 * 512];     // q rows 3584:4096
__device__ float g_s1[512 * 4096];   // head-1 scores (rows 3584:4096)
__device__ float g_s2[512 * 4096];   // head-2 scores
__device__ float g_vcol[4096];       // v[:,511]
__device__ float g_acol[512];        // attn_out[3584+j, 511]
__device__ float g_o[512];           // out_proj row
__device__ float g_m1[1024];
__device__ float g_m2[2048];
__device__ float g_logits[256];

// ---------------------------------------------------------------------------
// SGEMM (NT): C[m,n] = alpha * sum_k A[m,k]*W[n,k]  (+ bias[n]) (+ pe) (relu)
// Both operands are K-contiguous (row-major A, row-major W) -> dot-product GEMM.
// 128x128 tile, BK=8, 256 threads, 8x8 per-thread microtile, float4 I/O.
// All M,N divisible by 128 and K divisible by 8 for every call site.
// ---------------------------------------------------------------------------
template <bool RELU, bool ADDPE>
__global__ __launch_bounds__(256) void sgemm_nt(
    const float* __restrict__ A, const float* __restrict__ W,
    const float* __restrict__ bias, float* __restrict__ C,
    int K, int lda, int ldw, int ldc, float alpha)
{
    __shared__ float As[8][128];
    __shared__ float Ws[8][128];

    const int tid = threadIdx.x;
    const int bm = blockIdx.y, bn = blockIdx.x;
    const int tx = tid & 15;          // 16 thread cols
    const int ty = tid >> 4;          // 16 thread rows
    const int lr = tid >> 1;          // load row (0..127)
    const int lc = (tid & 1) << 2;    // load col4 (0 or 4)

    const float* Ab = A + (size_t)(bm * 128 + lr) * lda + lc;
    const float* Wb = W + (size_t)(bn * 128 + lr) * ldw + lc;

    float acc[8][8];
#pragma unroll
    for (int i = 0; i < 8; i++)
#pragma unroll
        for (int j = 0; j < 8; j++) acc[i][j] = 0.0f;

    for (int k0 = 0; k0 < K; k0 += 8) {
        float4 av = *(const float4*)(Ab + k0);
        float4 wv = *(const float4*)(Wb + k0);
        As[lc + 0][lr] = av.x; As[lc + 1][lr] = av.y;
        As[lc + 2][lr] = av.z; As[lc + 3][lr] = av.w;
        Ws[lc + 0][lr] = wv.x; Ws[lc + 1][lr] = wv.y;
        Ws[lc + 2][lr] = wv.z; Ws[lc + 3][lr] = wv.w;
        __syncthreads();

#pragma unroll
        for (int kk = 0; kk < 8; kk++) {
            float a[8], b[8];
            *(float4*)(a)     = *(const float4*)&As[kk][ty * 8];
            *(float4*)(a + 4) = *(const float4*)&As[kk][ty * 8 + 4];
            *(float4*)(b)     = *(const float4*)&Ws[kk][tx * 8];
            *(float4*)(b + 4) = *(const float4*)&Ws[kk][tx * 8 + 4];
#pragma unroll
            for (int i = 0; i < 8; i++)
#pragma unroll
                for (int j = 0; j < 8; j++)
                    acc[i][j] = fmaf(a[i], b[j], acc[i][j]);
        }
        __syncthreads();
    }

#pragma unroll
    for (int i = 0; i < 8; i++) {
        const int row = bm * 128 + ty * 8 + i;
#pragma unroll
        for (int j = 0; j < 8; j++) {
            const int col = bn * 128 + tx * 8 + j;
            float v = acc[i][j] * alpha;
            if (bias) v += __ldg(&bias[col]);
            if (ADDPE) {
                // pe[row, col]: div = exp(-(2*(col/2)) * ln(10000)/512)
                const int half = col >> 1;
                const float dv = expf(-(float)(2 * half) * (9.210340371976184f / 512.0f));
                const float arg = (float)row * dv;
                v += (col & 1) ? cosf(arg) : sinf(arg);
            }
            if (RELU) v = fmaxf(v, 0.0f);
            C[(size_t)row * ldc + col] = v;
        }
    }
}

// ---------------------------------------------------------------------------
// warp-per-output matvec: y[n] = [relu](dot(x, W[n,:]) + b[n])
// ---------------------------------------------------------------------------
__global__ void matvec_warp(const float* __restrict__ x, const float* __restrict__ W,
                            const float* __restrict__ b, float* __restrict__ y,
                            int N, int K, int relu)
{
    const int g = blockIdx.x * (blockDim.x >> 5) + (threadIdx.x >> 5);
    const int lane = threadIdx.x & 31;
    if (g >= N) return;
    const float* wr = W + (size_t)g * K;
    float s = 0.0f;
    for (int k = lane; k < K; k += 32) s = fmaf(x[k], wr[k], s);
#pragma unroll
    for (int o = 16; o; o >>= 1) s += __shfl_down_sync(0xffffffffu, s, o);
    if (lane == 0) {
        if (b) s += b[g];
        if (relu) s = fmaxf(s, 0.0f);
        y[g] = s;
    }
}

// v column 511: vcol[s] = dot(h[s,:], in_proj_w[1535,:]) + in_proj_b[1535]
__global__ void vcol_kernel(const float* __restrict__ h, const float* __restrict__ wrow,
                            const float* __restrict__ brow, float* __restrict__ vcol)
{
    const int g = blockIdx.x * (blockDim.x >> 5) + (threadIdx.x >> 5);
    const int lane = threadIdx.x & 31;
    if (g >= 4096) return;
    const float* hr = h + (size_t)g * 512;
    float s = 0.0f;
    for (int k = lane; k < 512; k += 32) s = fmaf(hr[k], wrow[k], s);
#pragma unroll
    for (int o = 16; o; o >>= 1) s += __shfl_down_sync(0xffffffffu, s, o);
    if (lane == 0) vcol[g] = s + *brow;
}

// block-wide reduce (all threads get the result)
__device__ __forceinline__ float blk_reduce(float v, float* red, bool ismax)
{
    const int tid = threadIdx.x;
    red[tid] = v;
    __syncthreads();
    for (int o = 128; o; o >>= 1) {
        if (tid < o) red[tid] = ismax ? fmaxf(red[tid], red[tid + o]) : (red[tid] + red[tid + o]);
        __syncthreads();
    }
    const float r = red[0];
    __syncthreads();
    return r;
}

// One block per attention row r (global row R = 3584+r):
// acol[r] = sum_s a1[R,s]*vcol[s] - lam * sum_s a2[R,s]*vcol[s] + sum_{s>R} vcol[s]
__global__ __launch_bounds__(256) void attn_row(
    const float* __restrict__ s1, const float* __restrict__ s2,
    const float* __restrict__ vcol, const float* __restrict__ lamp,
    float* __restrict__ acol)
{
    __shared__ float red[256];
    const int r = blockIdx.x;
    const int tid = threadIdx.x;
    const int R = 3584 + r;
    const float* r1 = s1 + (size_t)r * 4096;
    const float* r2 = s2 + (size_t)r * 4096;

    float m1 = -1e30f, m2 = -1e30f;
    for (int s = tid; s < 4096; s += 256) {
        m1 = fmaxf(m1, r1[s]);
        m2 = fmaxf(m2, r2[s]);
    }
    m1 = blk_reduce(m1, red, true);
    m2 = blk_reduce(m2, red, true);

    float e1 = 0.f, w1 = 0.f, e2 = 0.f, w2 = 0.f, suf = 0.f;
    for (int s = tid; s < 4096; s += 256) {
        const float v = vcol[s];
        const float a = expf(r1[s] - m1);
        const float b = expf(r2[s] - m2);
        e1 += a; w1 = fmaf(a, v, w1);
        e2 += b; w2 = fmaf(b, v, w2);
        if (s > R) suf += v;
    }
    e1 = blk_reduce(e1, red, false);
    w1 = blk_reduce(w1, red, false);
    e2 = blk_reduce(e2, red, false);
    w2 = blk_reduce(w2, red, false);
    suf = blk_reduce(suf, red, false);

    if (tid == 0) acol[r] = w1 / e1 - (*lamp) * (w2 / e2) + suf;
}

__global__ void softmax_out(const float* __restrict__ logits, float* __restrict__ out)
{
    __shared__ float red[256];
    const int tid = threadIdx.x;
    const float v = logits[tid];
    const float m = blk_reduce(v, red, true);
    const float e = expf(v - m);
    const float s = blk_reduce(e, red, false);
    out[tid] = e / s;
}

// ---------------------------------------------------------------------------
extern "C" void kernel_launch(void* const* d_in, const int* in_sizes, int n_in,
                              void* d_out, int out_size)
{
    const float* x          = (const float*)d_in[0];
    const float* enc_w1     = (const float*)d_in[1];
    const float* enc_b1     = (const float*)d_in[2];
    const float* enc_w2     = (const float*)d_in[3];
    const float* enc_b2     = (const float*)d_in[4];
    const float* enc_w3     = (const float*)d_in[5];
    const float* enc_b3     = (const float*)d_in[6];
    const float* enc_w4     = (const float*)d_in[7];
    const float* enc_b4     = (const float*)d_in[8];
    const float* in_proj_w  = (const float*)d_in[9];
    const float* in_proj_b  = (const float*)d_in[10];
    const float* out_proj_w = (const float*)d_in[11];
    const float* out_proj_b = (const float*)d_in[12];
    const float* lam        = (const float*)d_in[13];
    const float* act_w1     = (const float*)d_in[14];
    const float* act_b1     = (const float*)d_in[15];
    const float* act_w2     = (const float*)d_in[16];
    const float* act_b2     = (const float*)d_in[17];
    const float* act_w3     = (const float*)d_in[18];
    const float* act_b3     = (const float*)d_in[19];

    float *A, *B, *h, *k, *q, *s1, *s2, *vcol, *acol, *o, *m1, *m2, *lg;
    cudaGetSymbolAddress((void**)&A, g_A);
    cudaGetSymbolAddress((void**)&B, g_B);
    cudaGetSymbolAddress((void**)&h, g_h);
    cudaGetSymbolAddress((void**)&k, g_k);
    cudaGetSymbolAddress((void**)&q, g_q);
    cudaGetSymbolAddress((void**)&s1, g_s1);
    cudaGetSymbolAddress((void**)&s2, g_s2);
    cudaGetSymbolAddress((void**)&vcol, g_vcol);
    cudaGetSymbolAddress((void**)&acol, g_acol);
    cudaGetSymbolAddress((void**)&o, g_o);
    cudaGetSymbolAddress((void**)&m1, g_m1);
    cudaGetSymbolAddress((void**)&m2, g_m2);
    cudaGetSymbolAddress((void**)&lg, g_logits);

    // ---- encoder MLP (dominant cost, ~172 GFLOP) ----
    // h1 = relu(x @ enc_w1.T + b1): 4096x2048, K=1024
    sgemm_nt<true,  false><<<dim3(16, 32), 256>>>(x, enc_w1, enc_b1, A, 1024, 1024, 1024, 2048, 1.0f);
    // h2 = relu(h1 @ enc_w2.T + b2): 4096x4096, K=2048
    sgemm_nt<true,  false><<<dim3(32, 32), 256>>>(A, enc_w2, enc_b2, B, 2048, 2048, 2048, 4096, 1.0f);
    // h3 = relu(h2 @ enc_w3.T + b3): 4096x2048, K=4096
    sgemm_nt<true,  false><<<dim3(16, 32), 256>>>(B, enc_w3, enc_b3, A, 4096, 4096, 4096, 2048, 1.0f);
    // h = h3 @ enc_w4.T + b4 + pos_encoding: 4096x512, K=2048
    sgemm_nt<false, true ><<<dim3(4, 32), 256>>>(A, enc_w4, enc_b4, h, 2048, 2048, 2048, 512, 1.0f);

    // ---- qkv (pruned) ----
    // k (all rows): W rows 512..1023
    sgemm_nt<false, false><<<dim3(4, 32), 256>>>(h, in_proj_w + (size_t)512 * 512,
                                                 in_proj_b + 512, k, 512, 512, 512, 512, 1.0f);
    // q (rows 3584..4095): W rows 0..511
    sgemm_nt<false, false><<<dim3(4, 4), 256>>>(h + (size_t)3584 * 512, in_proj_w,
                                                in_proj_b, q, 512, 512, 512, 512, 1.0f);
    // v column 511: W row 1535
    vcol_kernel<<<512, 256>>>(h, in_proj_w + (size_t)1535 * 512, in_proj_b + 1535, vcol);

    // ---- attention scores (rows 3584:4096 only) ----
    const float scale = 0.7071067811865475f;  // 1/sqrt(HEAD_DIM)
    // s1 = q1 @ k1.T * scale : M=512, N=4096, K=256 (lda/ldw = 512)
    sgemm_nt<false, false><<<dim3(32, 4), 256>>>(q,       k,       nullptr, s1, 256, 512, 512, 4096, scale);
    // s2 = q2 @ k2.T * scale
    sgemm_nt<false, false><<<dim3(32, 4), 256>>>(q + 256, k + 256, nullptr, s2, 256, 512, 512, 4096, scale);

    // softmax + weighted sum over vcol + causal suffix -> acol[512]
    attn_row<<<512, 256>>>(s1, s2, vcol, lam, acol);

    // ---- final row through out_proj + act MLP (matvecs) ----
    matvec_warp<<<64, 256>>>(acol, out_proj_w, out_proj_b, o, 512, 512, 0);
    matvec_warp<<<128, 256>>>(o, act_w1, act_b1, m1, 1024, 512, 1);
    matvec_warp<<<256, 256>>>(m1, act_w2, act_b2, m2, 2048, 1024, 1);
    matvec_warp<<<32, 256>>>(m2, act_w3, act_b3, lg, 256, 2048, 0);

    softmax_out<<<1, 256>>>(lg, (float*)d_out);
}

// round 3
// speedup vs baseline: 2.1438x; 2.1438x over previous
#include <cuda_runtime.h>
#include <cuda_bf16.h>
#include <math.h>
#include <stdint.h>

// ===========================================================================
// S=4096, D_IN=1024, E=512, OUT=256, HEAD_DIM=2
// Output = softmax(row 4095 of post-attn MLP) -> pruned attention tail.
// Encoder GEMMs on tensor cores via mma.sync bf16 (compute_103-safe; no
// tcgen05 — the harness PTX targets sm_103 without the 'a' feature set),
// with 3-term bf16 split: C = Ahi*Bhi + Ahi*Blo + Alo*Bhi.
// ===========================================================================

// ---------------- scratch (__device__ globals; no cudaMalloc) --------------
__device__ __nv_bfloat16 g_xhi[4096*1024], g_xlo[4096*1024];
__device__ __nv_bfloat16 g_w1hi[2048*1024], g_w1lo[2048*1024];
__device__ __nv_bfloat16 g_w2hi[4096*2048], g_w2lo[4096*2048];
__device__ __nv_bfloat16 g_w3hi[2048*4096], g_w3lo[2048*4096];
__device__ __nv_bfloat16 g_w4hi[512*2048],  g_w4lo[512*2048];
__device__ __nv_bfloat16 g_h1hi[4096*2048], g_h1lo[4096*2048];
__device__ __nv_bfloat16 g_h2hi[4096*4096], g_h2lo[4096*4096];
__device__ __nv_bfloat16 g_h3hi[4096*2048], g_h3lo[4096*2048];

__device__ float g_h[4096 * 512];
__device__ float g_k[4096 * 512];
__device__ float g_q[512 * 512];
__device__ float g_s1[512 * 4096];
__device__ float g_s2[512 * 4096];
__device__ float g_vcol[4096];
__device__ float g_acol[512];
__device__ float g_o[512];
__device__ float g_m1[1024];
__device__ float g_m2[2048];
__device__ float g_logits[256];

// ---------------- PTX helpers ----------------------------------------------
__device__ __forceinline__ uint32_t smem_u32(const void* p) {
    uint32_t a;
    asm("{ .reg .u64 t; cvta.to.shared.u64 t, %1; cvt.u32.u64 %0, t; }" : "=r"(a) : "l"(p));
    return a;
}

#define CP_ASYNC16(dst, src) \
    asm volatile("cp.async.cg.shared.global [%0], [%1], 16;\n" :: "r"(dst), "l"(src))
#define CP_COMMIT() asm volatile("cp.async.commit_group;\n" ::: "memory")
#define CP_WAIT(n)  asm volatile("cp.async.wait_group %0;\n" :: "n"(n) : "memory")

__device__ __forceinline__ void ldm_x4(uint32_t* r, uint32_t addr) {
    asm volatile("ldmatrix.sync.aligned.m8n8.x4.shared.b16 {%0,%1,%2,%3}, [%4];"
                 : "=r"(r[0]), "=r"(r[1]), "=r"(r[2]), "=r"(r[3]) : "r"(addr));
}

__device__ __forceinline__ void mma_bf16(float* c, const uint32_t* a, uint32_t b0, uint32_t b1) {
    asm volatile(
        "mma.sync.aligned.m16n8k16.row.col.f32.bf16.bf16.f32 "
        "{%0,%1,%2,%3}, {%4,%5,%6,%7}, {%8,%9}, {%0,%1,%2,%3};"
        : "+f"(c[0]), "+f"(c[1]), "+f"(c[2]), "+f"(c[3])
        : "r"(a[0]), "r"(a[1]), "r"(a[2]), "r"(a[3]), "r"(b0), "r"(b1));
}

__device__ __forceinline__ uint32_t pack_bf2(float v0, float v1) {
    __nv_bfloat16 h0 = __float2bfloat16(v0), h1 = __float2bfloat16(v1);
    return (uint32_t)__bfloat16_as_ushort(h0) | ((uint32_t)__bfloat16_as_ushort(h1) << 16);
}

// ---------------------------------------------------------------------------
// fp32 -> bf16 hi/lo split (elementwise)
// ---------------------------------------------------------------------------
__global__ void split_f32(const float* __restrict__ in, __nv_bfloat16* __restrict__ hi,
                          __nv_bfloat16* __restrict__ lo, int n)
{
    int i = (blockIdx.x * blockDim.x + threadIdx.x) * 4;
    if (i >= n) return;
    float4 v = *(const float4*)(in + i);
    __nv_bfloat16 h0 = __float2bfloat16(v.x), h1 = __float2bfloat16(v.y);
    __nv_bfloat16 h2 = __float2bfloat16(v.z), h3 = __float2bfloat16(v.w);
    uint32_t hp0 = pack_bf2(v.x, v.y), hp1 = pack_bf2(v.z, v.w);
    uint32_t lp0 = pack_bf2(v.x - __bfloat162float(h0), v.y - __bfloat162float(h1));
    uint32_t lp1 = pack_bf2(v.z - __bfloat162float(h2), v.w - __bfloat162float(h3));
    *(uint2*)(hi + i) = make_uint2(hp0, hp1);
    *(uint2*)(lo + i) = make_uint2(lp0, lp1);
}

// ---------------------------------------------------------------------------
// mma.sync bf16 split-GEMM.
// C[M,N] = sum_k A[m,k]*B[n,k] with A = Ahi+Alo, B = Bhi+Blo (drop lo*lo).
// CTA: 128(M, blockIdx.y) x 128(N, blockIdx.x), BK=32, 256 thr (8 warps 4x2,
// each warp 32x64). Double-buffered cp.async; padded smem rows (80B) for
// conflict-free ldmatrix.
// EPI=0: v = relu(acc+bias) -> bf16 hi/lo split outputs
// EPI=1: v = acc+bias+pos_encoding -> fp32 output
// smem per stage: 4 tiles (Ahi,Alo,Bhi,Blo), each 128 rows * 80B = 10240B.
// ---------------------------------------------------------------------------
template <int EPI>
__global__ __launch_bounds__(256) void mma_gemm(
    const __nv_bfloat16* __restrict__ Ahi, const __nv_bfloat16* __restrict__ Alo,
    const __nv_bfloat16* __restrict__ Bhi, const __nv_bfloat16* __restrict__ Blo,
    const float* __restrict__ bias,
    __nv_bfloat16* __restrict__ Chi, __nv_bfloat16* __restrict__ Clo,
    float* __restrict__ Cf, int K, int N)
{
    extern __shared__ char smem[];
    const uint32_t sb = smem_u32(smem);
    const int tid = threadIdx.x;
    const int wid = tid >> 5;
    const int lane = tid & 31;
    const int warp_m = wid >> 1;      // 0..3
    const int warp_n = wid & 1;       // 0..1
    const int bm = blockIdx.y, bn = blockIdx.x;

    const __nv_bfloat16* gptr[4] = {
        Ahi + (size_t)bm * 128 * K, Alo + (size_t)bm * 128 * K,
        Bhi + (size_t)bn * 128 * K, Blo + (size_t)bn * 128 * K };

    auto load_tile = [&](int s, int k0) {
#pragma unroll
        for (int i = 0; i < 8; i++) {
            int idx = tid + i * 256;          // 0..2047 chunks of 16B
            int t   = idx >> 9;               // tensor 0..3
            int row = (idx >> 2) & 127;
            int c   = idx & 3;
            uint32_t dst = sb + s * 40960 + t * 10240 + row * 80 + c * 16;
            CP_ASYNC16(dst, gptr[t] + (size_t)row * K + k0 + c * 8);
        }
    };

    float acc[2][8][4];
#pragma unroll
    for (int i = 0; i < 2; i++)
#pragma unroll
        for (int j = 0; j < 8; j++)
#pragma unroll
            for (int l = 0; l < 4; l++) acc[i][j][l] = 0.0f;

    const int T = K >> 5;
    load_tile(0, 0);
    CP_COMMIT();

    for (int t = 0; t < T; t++) {
        const int buf = t & 1;
        if (t + 1 < T) { load_tile(buf ^ 1, (t + 1) << 5); CP_COMMIT(); CP_WAIT(1); }
        else           { CP_WAIT(0); }
        __syncthreads();

        const uint32_t sa = sb + buf * 40960;
#pragma unroll
        for (int ks = 0; ks < 2; ks++) {
            const int kb = ks * 32 + ((lane >= 16) ? 16 : 0);
            const int lr = lane & 15;

            uint32_t ah[2][4], al[2][4];
#pragma unroll
            for (int mf = 0; mf < 2; mf++) {
                uint32_t addr = sa + (uint32_t)(warp_m * 32 + mf * 16 + lr) * 80 + kb;
                ldm_x4(ah[mf], addr);
                ldm_x4(al[mf], addr + 10240);
            }
            uint32_t bh[4][4], bl[4][4];
#pragma unroll
            for (int bt = 0; bt < 4; bt++) {
                uint32_t addr = sa + 20480 + (uint32_t)(warp_n * 64 + bt * 16 + lr) * 80 + kb;
                ldm_x4(bh[bt], addr);
                ldm_x4(bl[bt], addr + 10240);
            }
#pragma unroll
            for (int mf = 0; mf < 2; mf++)
#pragma unroll
                for (int bt = 0; bt < 4; bt++) {
                    // n-frag 2*bt uses regs {0,2}; n-frag 2*bt+1 uses {1,3}
                    mma_bf16(acc[mf][2 * bt],     ah[mf], bh[bt][0], bh[bt][2]);
                    mma_bf16(acc[mf][2 * bt + 1], ah[mf], bh[bt][1], bh[bt][3]);
                    mma_bf16(acc[mf][2 * bt],     ah[mf], bl[bt][0], bl[bt][2]);
                    mma_bf16(acc[mf][2 * bt + 1], ah[mf], bl[bt][1], bl[bt][3]);
                    mma_bf16(acc[mf][2 * bt],     al[mf], bh[bt][0], bh[bt][2]);
                    mma_bf16(acc[mf][2 * bt + 1], al[mf], bh[bt][1], bh[bt][3]);
                }
        }
        __syncthreads();
    }

    // ---- epilogue ----
    const int rbase = bm * 128 + warp_m * 32 + (lane >> 2);
    const int cbase = bn * 128 + warp_n * 64 + (lane & 3) * 2;
#pragma unroll
    for (int mf = 0; mf < 2; mf++) {
#pragma unroll
        for (int nf = 0; nf < 8; nf++) {
            const int c0 = cbase + nf * 8;          // even
            const float b0 = __ldg(&bias[c0]), b1 = __ldg(&bias[c0 + 1]);
#pragma unroll
            for (int rr = 0; rr < 2; rr++) {
                const int row = rbase + mf * 16 + rr * 8;
                float v0 = acc[mf][nf][rr * 2]     + b0;
                float v1 = acc[mf][nf][rr * 2 + 1] + b1;
                if (EPI == 0) {
                    v0 = fmaxf(v0, 0.0f); v1 = fmaxf(v1, 0.0f);
                    __nv_bfloat16 h0 = __float2bfloat16(v0), h1 = __float2bfloat16(v1);
                    float l0 = v0 - __bfloat162float(h0), l1 = v1 - __bfloat162float(h1);
                    *(uint32_t*)(Chi + (size_t)row * N + c0) =
                        (uint32_t)__bfloat16_as_ushort(h0) |
                        ((uint32_t)__bfloat16_as_ushort(h1) << 16);
                    *(uint32_t*)(Clo + (size_t)row * N + c0) = pack_bf2(l0, l1);
                } else {
                    const float dv = expf(-(float)c0 * (9.210340371976184f / 512.0f));
                    const float arg = (float)row * dv;
                    v0 += sinf(arg);
                    v1 += cosf(arg);
                    *(float2*)(Cf + (size_t)row * N + c0) = make_float2(v0, v1);
                }
            }
        }
    }
}

// ---------------------------------------------------------------------------
// Scalar SGEMM (NT) — small pruned ops (k, q, scores)
// ---------------------------------------------------------------------------
template <bool RELU>
__global__ __launch_bounds__(256) void sgemm_nt(
    const float* __restrict__ A, const float* __restrict__ W,
    const float* __restrict__ bias, float* __restrict__ C,
    int K, int lda, int ldw, int ldc, float alpha)
{
    __shared__ float As[8][128];
    __shared__ float Ws[8][128];

    const int tid = threadIdx.x;
    const int bm = blockIdx.y, bn = blockIdx.x;
    const int tx = tid & 15;
    const int ty = tid >> 4;
    const int lr = tid >> 1;
    const int lc = (tid & 1) << 2;

    const float* Ab = A + (size_t)(bm * 128 + lr) * lda + lc;
    const float* Wb = W + (size_t)(bn * 128 + lr) * ldw + lc;

    float acc[8][8];
#pragma unroll
    for (int i = 0; i < 8; i++)
#pragma unroll
        for (int j = 0; j < 8; j++) acc[i][j] = 0.0f;

    for (int k0 = 0; k0 < K; k0 += 8) {
        float4 av = *(const float4*)(Ab + k0);
        float4 wv = *(const float4*)(Wb + k0);
        As[lc + 0][lr] = av.x; As[lc + 1][lr] = av.y;
        As[lc + 2][lr] = av.z; As[lc + 3][lr] = av.w;
        Ws[lc + 0][lr] = wv.x; Ws[lc + 1][lr] = wv.y;
        Ws[lc + 2][lr] = wv.z; Ws[lc + 3][lr] = wv.w;
        __syncthreads();

#pragma unroll
        for (int kk = 0; kk < 8; kk++) {
            float a[8], b[8];
            *(float4*)(a)     = *(const float4*)&As[kk][ty * 8];
            *(float4*)(a + 4) = *(const float4*)&As[kk][ty * 8 + 4];
            *(float4*)(b)     = *(const float4*)&Ws[kk][tx * 8];
            *(float4*)(b + 4) = *(const float4*)&Ws[kk][tx * 8 + 4];
#pragma unroll
            for (int i = 0; i < 8; i++)
#pragma unroll
                for (int j = 0; j < 8; j++)
                    acc[i][j] = fmaf(a[i], b[j], acc[i][j]);
        }
        __syncthreads();
    }

#pragma unroll
    for (int i = 0; i < 8; i++) {
        const int row = bm * 128 + ty * 8 + i;
#pragma unroll
        for (int j = 0; j < 8; j++) {
            const int col = bn * 128 + tx * 8 + j;
            float v = acc[i][j] * alpha;
            if (bias) v += __ldg(&bias[col]);
            if (RELU) v = fmaxf(v, 0.0f);
            C[(size_t)row * ldc + col] = v;
        }
    }
}

// ---------------------------------------------------------------------------
__global__ void matvec_warp(const float* __restrict__ x, const float* __restrict__ W,
                            const float* __restrict__ b, float* __restrict__ y,
                            int N, int K, int relu)
{
    const int g = blockIdx.x * (blockDim.x >> 5) + (threadIdx.x >> 5);
    const int lane = threadIdx.x & 31;
    if (g >= N) return;
    const float* wr = W + (size_t)g * K;
    float s = 0.0f;
    for (int k = lane; k < K; k += 32) s = fmaf(x[k], wr[k], s);
#pragma unroll
    for (int o = 16; o; o >>= 1) s += __shfl_down_sync(0xffffffffu, s, o);
    if (lane == 0) {
        if (b) s += b[g];
        if (relu) s = fmaxf(s, 0.0f);
        y[g] = s;
    }
}

__global__ void vcol_kernel(const float* __restrict__ h, const float* __restrict__ wrow,
                            const float* __restrict__ brow, float* __restrict__ vcol)
{
    const int g = blockIdx.x * (blockDim.x >> 5) + (threadIdx.x >> 5);
    const int lane = threadIdx.x & 31;
    if (g >= 4096) return;
    const float* hr = h + (size_t)g * 512;
    float s = 0.0f;
    for (int k = lane; k < 512; k += 32) s = fmaf(hr[k], wrow[k], s);
#pragma unroll
    for (int o = 16; o; o >>= 1) s += __shfl_down_sync(0xffffffffu, s, o);
    if (lane == 0) vcol[g] = s + *brow;
}

__device__ __forceinline__ float blk_reduce(float v, float* red, bool ismax)
{
    const int tid = threadIdx.x;
    red[tid] = v;
    __syncthreads();
    for (int o = 128; o; o >>= 1) {
        if (tid < o) red[tid] = ismax ? fmaxf(red[tid], red[tid + o]) : (red[tid] + red[tid + o]);
        __syncthreads();
    }
    const float r = red[0];
    __syncthreads();
    return r;
}

__global__ __launch_bounds__(256) void attn_row(
    const float* __restrict__ s1, const float* __restrict__ s2,
    const float* __restrict__ vcol, const float* __restrict__ lamp,
    float* __restrict__ acol)
{
    __shared__ float red[256];
    const int r = blockIdx.x;
    const int tid = threadIdx.x;
    const int R = 3584 + r;
    const float* r1 = s1 + (size_t)r * 4096;
    const float* r2 = s2 + (size_t)r * 4096;

    float m1 = -1e30f, m2 = -1e30f;
    for (int s = tid; s < 4096; s += 256) {
        m1 = fmaxf(m1, r1[s]);
        m2 = fmaxf(m2, r2[s]);
    }
    m1 = blk_reduce(m1, red, true);
    m2 = blk_reduce(m2, red, true);

    float e1 = 0.f, w1 = 0.f, e2 = 0.f, w2 = 0.f, suf = 0.f;
    for (int s = tid; s < 4096; s += 256) {
        const float v = vcol[s];
        const float a = expf(r1[s] - m1);
        const float b = expf(r2[s] - m2);
        e1 += a; w1 = fmaf(a, v, w1);
        e2 += b; w2 = fmaf(b, v, w2);
        if (s > R) suf += v;
    }
    e1 = blk_reduce(e1, red, false);
    w1 = blk_reduce(w1, red, false);
    e2 = blk_reduce(e2, red, false);
    w2 = blk_reduce(w2, red, false);
    suf = blk_reduce(suf, red, false);

    if (tid == 0) acol[r] = w1 / e1 - (*lamp) * (w2 / e2) + suf;
}

__global__ void softmax_out(const float* __restrict__ logits, float* __restrict__ out)
{
    __shared__ float red[256];
    const int tid = threadIdx.x;
    const float v = logits[tid];
    const float m = blk_reduce(v, red, true);
    const float e = expf(v - m);
    const float s = blk_reduce(e, red, false);
    out[tid] = e / s;
}

// ---------------------------------------------------------------------------
extern "C" void kernel_launch(void* const* d_in, const int* in_sizes, int n_in,
                              void* d_out, int out_size)
{
    const float* x          = (const float*)d_in[0];
    const float* enc_w1     = (const float*)d_in[1];
    const float* enc_b1     = (const float*)d_in[2];
    const float* enc_w2     = (const float*)d_in[3];
    const float* enc_b2     = (const float*)d_in[4];
    const float* enc_w3     = (const float*)d_in[5];
    const float* enc_b3     = (const float*)d_in[6];
    const float* enc_w4     = (const float*)d_in[7];
    const float* enc_b4     = (const float*)d_in[8];
    const float* in_proj_w  = (const float*)d_in[9];
    const float* in_proj_b  = (const float*)d_in[10];
    const float* out_proj_w = (const float*)d_in[11];
    const float* out_proj_b = (const float*)d_in[12];
    const float* lam        = (const float*)d_in[13];
    const float* act_w1     = (const float*)d_in[14];
    const float* act_b1     = (const float*)d_in[15];
    const float* act_w2     = (const float*)d_in[16];
    const float* act_b2     = (const float*)d_in[17];
    const float* act_w3     = (const float*)d_in[18];
    const float* act_b3     = (const float*)d_in[19];

    __nv_bfloat16 *xhi, *xlo, *w1hi, *w1lo, *w2hi, *w2lo, *w3hi, *w3lo, *w4hi, *w4lo;
    __nv_bfloat16 *h1hi, *h1lo, *h2hi, *h2lo, *h3hi, *h3lo;
    float *h, *k, *q, *s1, *s2, *vcol, *acol, *o, *m1, *m2, *lg;
    cudaGetSymbolAddress((void**)&xhi, g_xhi);   cudaGetSymbolAddress((void**)&xlo, g_xlo);
    cudaGetSymbolAddress((void**)&w1hi, g_w1hi); cudaGetSymbolAddress((void**)&w1lo, g_w1lo);
    cudaGetSymbolAddress((void**)&w2hi, g_w2hi); cudaGetSymbolAddress((void**)&w2lo, g_w2lo);
    cudaGetSymbolAddress((void**)&w3hi, g_w3hi); cudaGetSymbolAddress((void**)&w3lo, g_w3lo);
    cudaGetSymbolAddress((void**)&w4hi, g_w4hi); cudaGetSymbolAddress((void**)&w4lo, g_w4lo);
    cudaGetSymbolAddress((void**)&h1hi, g_h1hi); cudaGetSymbolAddress((void**)&h1lo, g_h1lo);
    cudaGetSymbolAddress((void**)&h2hi, g_h2hi); cudaGetSymbolAddress((void**)&h2lo, g_h2lo);
    cudaGetSymbolAddress((void**)&h3hi, g_h3hi); cudaGetSymbolAddress((void**)&h3lo, g_h3lo);
    cudaGetSymbolAddress((void**)&h, g_h);
    cudaGetSymbolAddress((void**)&k, g_k);
    cudaGetSymbolAddress((void**)&q, g_q);
    cudaGetSymbolAddress((void**)&s1, g_s1);
    cudaGetSymbolAddress((void**)&s2, g_s2);
    cudaGetSymbolAddress((void**)&vcol, g_vcol);
    cudaGetSymbolAddress((void**)&acol, g_acol);
    cudaGetSymbolAddress((void**)&o, g_o);
    cudaGetSymbolAddress((void**)&m1, g_m1);
    cudaGetSymbolAddress((void**)&m2, g_m2);
    cudaGetSymbolAddress((void**)&lg, g_logits);

    const int SMEM_MMA = 2 * 40960;  // 81920 B dynamic smem
    cudaFuncSetAttribute(mma_gemm<0>, cudaFuncAttributeMaxDynamicSharedMemorySize, SMEM_MMA);
    cudaFuncSetAttribute(mma_gemm<1>, cudaFuncAttributeMaxDynamicSharedMemorySize, SMEM_MMA);

    // ---- bf16 splits of x and encoder weights ----
    split_f32<<<4096 * 1024 / 1024, 256>>>(x, xhi, xlo, 4096 * 1024);
    split_f32<<<2048 * 1024 / 1024, 256>>>(enc_w1, w1hi, w1lo, 2048 * 1024);
    split_f32<<<4096 * 2048 / 1024, 256>>>(enc_w2, w2hi, w2lo, 4096 * 2048);
    split_f32<<<2048 * 4096 / 1024, 256>>>(enc_w3, w3hi, w3lo, 2048 * 4096);
    split_f32<<<512 * 2048 / 1024, 256>>>(enc_w4, w4hi, w4lo, 512 * 2048);

    // ---- encoder on tensor cores ----
    // h1 = relu(x @ w1^T + b1): M=4096, N=2048, K=1024
    mma_gemm<0><<<dim3(16, 32), 256, SMEM_MMA>>>(xhi, xlo, w1hi, w1lo, enc_b1,
                                                 h1hi, h1lo, nullptr, 1024, 2048);
    // h2 = relu(h1 @ w2^T + b2): N=4096, K=2048
    mma_gemm<0><<<dim3(32, 32), 256, SMEM_MMA>>>(h1hi, h1lo, w2hi, w2lo, enc_b2,
                                                 h2hi, h2lo, nullptr, 2048, 4096);
    // h3 = relu(h2 @ w3^T + b3): N=2048, K=4096
    mma_gemm<0><<<dim3(16, 32), 256, SMEM_MMA>>>(h2hi, h2lo, w3hi, w3lo, enc_b3,
                                                 h3hi, h3lo, nullptr, 4096, 2048);
    // h = h3 @ w4^T + b4 + pos_encoding: N=512, K=2048 (fp32 out)
    mma_gemm<1><<<dim3(4, 32), 256, SMEM_MMA>>>(h3hi, h3lo, w4hi, w4lo, enc_b4,
                                                nullptr, nullptr, h, 2048, 512);

    // ---- pruned qkv (scalar) ----
    sgemm_nt<false><<<dim3(4, 32), 256>>>(h, in_proj_w + (size_t)512 * 512,
                                          in_proj_b + 512, k, 512, 512, 512, 512, 1.0f);
    sgemm_nt<false><<<dim3(4, 4), 256>>>(h + (size_t)3584 * 512, in_proj_w,
                                         in_proj_b, q, 512, 512, 512, 512, 1.0f);
    vcol_kernel<<<512, 256>>>(h, in_proj_w + (size_t)1535 * 512, in_proj_b + 1535, vcol);

    // ---- attention scores (rows 3584:4096) ----
    const float scale = 0.7071067811865475f;
    sgemm_nt<false><<<dim3(32, 4), 256>>>(q,       k,       nullptr, s1, 256, 512, 512, 4096, scale);
    sgemm_nt<false><<<dim3(32, 4), 256>>>(q + 256, k + 256, nullptr, s2, 256, 512, 512, 4096, scale);

    attn_row<<<512, 256>>>(s1, s2, vcol, lam, acol);

    // ---- final-row MLP ----
    matvec_warp<<<64, 256>>>(acol, out_proj_w, out_proj_b, o, 512, 512, 0);
    matvec_warp<<<128, 256>>>(o, act_w1, act_b1, m1, 1024, 512, 1);
    matvec_warp<<<256, 256>>>(m1, act_w2, act_b2, m2, 2048, 1024, 1);
    matvec_warp<<<32, 256>>>(m2, act_w3, act_b3, lg, 256, 2048, 0);

    softmax_out<<<1, 256>>>(lg, (float*)d_out);
}

// round 8
// speedup vs baseline: 2.2847x; 1.0657x over previous
#include <cuda_runtime.h>
#include <cuda_bf16.h>
#include <math.h>
#include <stdint.h>

// ===========================================================================
// S=4096, D_IN=1024, E=512, OUT=256, HEAD_DIM=2
// Output = softmax(row 4095 of post-attn MLP) -> pruned attention tail.
// Encoder GEMMs + k-projection on tensor cores via mma.sync bf16
// (compute_103-safe), 3-term split: C = Ahi*Bhi + Ahi*Blo + Alo*Bhi.
// R4..R8: 64x64 warp tiles (4 warps/CTA) -> 85 B smem per HMMA (was 128).
// ===========================================================================

// ---------------- scratch (__device__ globals; no cudaMalloc) --------------
__device__ __nv_bfloat16 g_xhi[4096*1024], g_xlo[4096*1024];
__device__ __nv_bfloat16 g_w1hi[2048*1024], g_w1lo[2048*1024];
__device__ __nv_bfloat16 g_w2hi[4096*2048], g_w2lo[4096*2048];
__device__ __nv_bfloat16 g_w3hi[2048*4096], g_w3lo[2048*4096];
__device__ __nv_bfloat16 g_w4hi[512*2048],  g_w4lo[512*2048];
__device__ __nv_bfloat16 g_h1hi[4096*2048], g_h1lo[4096*2048];
__device__ __nv_bfloat16 g_h2hi[4096*4096], g_h2lo[4096*4096];
__device__ __nv_bfloat16 g_h3hi[4096*2048], g_h3lo[4096*2048];
__device__ __nv_bfloat16 g_hhi[4096*512],   g_hlo[4096*512];
__device__ __nv_bfloat16 g_wkhi[512*512],   g_wklo[512*512];

__device__ float g_h[4096 * 512];
__device__ float g_k[4096 * 512];
__device__ float g_q[512 * 512];
__device__ float g_s1[512 * 4096];
__device__ float g_s2[512 * 4096];
__device__ float g_vcol[4096];
__device__ float g_acol[512];
__device__ float g_o[512];
__device__ float g_m1[1024];
__device__ float g_m2[2048];
__device__ float g_logits[256];

// ---------------- PTX helpers ----------------------------------------------
__device__ __forceinline__ uint32_t smem_u32(const void* p) {
    uint32_t a;
    asm("{ .reg .u64 t; cvta.to.shared.u64 t, %1; cvt.u32.u64 %0, t; }" : "=r"(a) : "l"(p));
    return a;
}

#define CP_ASYNC16(dst, src) \
    asm volatile("cp.async.cg.shared.global [%0], [%1], 16;\n" :: "r"(dst), "l"(src))
#define CP_COMMIT() asm volatile("cp.async.commit_group;\n" ::: "memory")
#define CP_WAIT(n)  asm volatile("cp.async.wait_group %0;\n" :: "n"(n) : "memory")

__device__ __forceinline__ void ldm_x4(uint32_t* r, uint32_t addr) {
    asm volatile("ldmatrix.sync.aligned.m8n8.x4.shared.b16 {%0,%1,%2,%3}, [%4];"
                 : "=r"(r[0]), "=r"(r[1]), "=r"(r[2]), "=r"(r[3]) : "r"(addr));
}

__device__ __forceinline__ void mma_bf16(float* c, const uint32_t* a, uint32_t b0, uint32_t b1) {
    asm volatile(
        "mma.sync.aligned.m16n8k16.row.col.f32.bf16.bf16.f32 "
        "{%0,%1,%2,%3}, {%4,%5,%6,%7}, {%8,%9}, {%0,%1,%2,%3};"
        : "+f"(c[0]), "+f"(c[1]), "+f"(c[2]), "+f"(c[3])
        : "r"(a[0]), "r"(a[1]), "r"(a[2]), "r"(a[3]), "r"(b0), "r"(b1));
}

__device__ __forceinline__ uint32_t pack_bf2(float v0, float v1) {
    __nv_bfloat16 h0 = __float2bfloat16(v0), h1 = __float2bfloat16(v1);
    return (uint32_t)__bfloat16_as_ushort(h0) | ((uint32_t)__bfloat16_as_ushort(h1) << 16);
}

// ---------------------------------------------------------------------------
__global__ void split_f32(const float* __restrict__ in, __nv_bfloat16* __restrict__ hi,
                          __nv_bfloat16* __restrict__ lo, int n)
{
    int i = (blockIdx.x * blockDim.x + threadIdx.x) * 4;
    if (i >= n) return;
    float4 v = *(const float4*)(in + i);
    __nv_bfloat16 h0 = __float2bfloat16(v.x), h1 = __float2bfloat16(v.y);
    __nv_bfloat16 h2 = __float2bfloat16(v.z), h3 = __float2bfloat16(v.w);
    uint32_t hp0 = pack_bf2(v.x, v.y), hp1 = pack_bf2(v.z, v.w);
    uint32_t lp0 = pack_bf2(v.x - __bfloat162float(h0), v.y - __bfloat162float(h1));
    uint32_t lp1 = pack_bf2(v.z - __bfloat162float(h2), v.w - __bfloat162float(h3));
    *(uint2*)(hi + i) = make_uint2(hp0, hp1);
    *(uint2*)(lo + i) = make_uint2(lp0, lp1);
}

// ---------------------------------------------------------------------------
// mma.sync bf16 split-GEMM. C[M,N] = sum_k A[m,k]*B[n,k] (3-term split).
// CTA: 128x128, BK=32, 128 threads = 4 warps in 2x2, each warp 64x64.
// EPI=0: relu(acc+bias)        -> bf16 hi/lo
// EPI=1: acc+bias+PE           -> fp32 AND bf16 hi/lo
// EPI=2: acc+bias              -> fp32
// smem/stage: 4 tiles (Ahi,Alo,Bhi,Blo) x 128 rows x 80B = 40960B.
// ---------------------------------------------------------------------------
template <int EPI>
__global__ __launch_bounds__(128) void mma_gemm(
    const __nv_bfloat16* __restrict__ Ahi, const __nv_bfloat16* __restrict__ Alo,
    const __nv_bfloat16* __restrict__ Bhi, const __nv_bfloat16* __restrict__ Blo,
    const float* __restrict__ bias,
    __nv_bfloat16* __restrict__ Chi, __nv_bfloat16* __restrict__ Clo,
    float* __restrict__ Cf, int K, int N)
{
    extern __shared__ char smem[];
    const uint32_t sb = smem_u32(smem);
    const int tid = threadIdx.x;
    const int wid = tid >> 5;
    const int lane = tid & 31;
    const int warp_m = wid >> 1;      // 0..1 -> 64 rows
    const int warp_n = wid & 1;       // 0..1 -> 64 cols
    const int bm = blockIdx.y, bn = blockIdx.x;

    const __nv_bfloat16* gptr[4] = {
        Ahi + (size_t)bm * 128 * K, Alo + (size_t)bm * 128 * K,
        Bhi + (size_t)bn * 128 * K, Blo + (size_t)bn * 128 * K };

    auto load_tile = [&](int s, int k0) {
#pragma unroll
        for (int i = 0; i < 16; i++) {
            int idx = tid + i * 128;          // 0..2047 chunks of 16B
            int t   = idx >> 9;               // tensor 0..3
            int row = (idx >> 2) & 127;
            int c   = idx & 3;
            uint32_t dst = sb + s * 40960 + t * 10240 + row * 80 + c * 16;
            CP_ASYNC16(dst, gptr[t] + (size_t)row * K + k0 + c * 8);
        }
    };

    float acc[4][8][4];
#pragma unroll
    for (int i = 0; i < 4; i++)
#pragma unroll
        for (int j = 0; j < 8; j++)
#pragma unroll
            for (int l = 0; l < 4; l++) acc[i][j][l] = 0.0f;

    const int T = K >> 5;
    load_tile(0, 0);
    CP_COMMIT();

    for (int t = 0; t < T; t++) {
        const int buf = t & 1;
        if (t + 1 < T) { load_tile(buf ^ 1, (t + 1) << 5); CP_COMMIT(); CP_WAIT(1); }
        else           { CP_WAIT(0); }
        __syncthreads();

        const uint32_t sa = sb + buf * 40960;
#pragma unroll
        for (int ks = 0; ks < 2; ks++) {
            const int kb = ks * 32 + ((lane >= 16) ? 16 : 0);
            const int lr = lane & 15;

            uint32_t ah[4][4], al[4][4];
#pragma unroll
            for (int mf = 0; mf < 4; mf++) {
                uint32_t addr = sa + (uint32_t)(warp_m * 64 + mf * 16 + lr) * 80 + kb;
                ldm_x4(ah[mf], addr);
                ldm_x4(al[mf], addr + 10240);
            }
#pragma unroll
            for (int bt = 0; bt < 4; bt++) {
                uint32_t bh[4], bl[4];
                uint32_t addr = sa + 20480 + (uint32_t)(warp_n * 64 + bt * 16 + lr) * 80 + kb;
                ldm_x4(bh, addr);
                ldm_x4(bl, addr + 10240);
#pragma unroll
                for (int mf = 0; mf < 4; mf++) {
                    mma_bf16(acc[mf][2 * bt],     ah[mf], bh[0], bh[2]);
                    mma_bf16(acc[mf][2 * bt + 1], ah[mf], bh[1], bh[3]);
                    mma_bf16(acc[mf][2 * bt],     ah[mf], bl[0], bl[2]);
                    mma_bf16(acc[mf][2 * bt + 1], ah[mf], bl[1], bl[3]);
                    mma_bf16(acc[mf][2 * bt],     al[mf], bh[0], bh[2]);
                    mma_bf16(acc[mf][2 * bt + 1], al[mf], bh[1], bh[3]);
                }
            }
        }
        __syncthreads();
    }

    // ---- epilogue ----
    const int rbase = bm * 128 + warp_m * 64 + (lane >> 2);
    const int cbase = bn * 128 + warp_n * 64 + (lane & 3) * 2;
#pragma unroll
    for (int mf = 0; mf < 4; mf++) {
#pragma unroll
        for (int nf = 0; nf < 8; nf++) {
            const int c0 = cbase + nf * 8;          // even column
            const float b0 = __ldg(&bias[c0]), b1 = __ldg(&bias[c0 + 1]);
#pragma unroll
            for (int rr = 0; rr < 2; rr++) {
                const int row = rbase + mf * 16 + rr * 8;
                float v0 = acc[mf][nf][rr * 2]     + b0;
                float v1 = acc[mf][nf][rr * 2 + 1] + b1;
                if (EPI == 1) {
                    const float dv = expf(-(float)c0 * (9.210340371976184f / 512.0f));
                    const float arg = (float)row * dv;
                    v0 += sinf(arg);
                    v1 += cosf(arg);
                }
                if (EPI == 0) {
                    v0 = fmaxf(v0, 0.0f); v1 = fmaxf(v1, 0.0f);
                }
                if (EPI == 0 || EPI == 1) {
                    __nv_bfloat16 h0 = __float2bfloat16(v0), h1 = __float2bfloat16(v1);
                    float l0 = v0 - __bfloat162float(h0), l1 = v1 - __bfloat162float(h1);
                    *(uint32_t*)(Chi + (size_t)row * N + c0) =
                        (uint32_t)__bfloat16_as_ushort(h0) |
                        ((uint32_t)__bfloat16_as_ushort(h1) << 16);
                    *(uint32_t*)(Clo + (size_t)row * N + c0) = pack_bf2(l0, l1);
                }
                if (EPI == 1 || EPI == 2) {
                    *(float2*)(Cf + (size_t)row * N + c0) = make_float2(v0, v1);
                }
            }
        }
    }
}

// ---------------------------------------------------------------------------
// Scalar SGEMM (NT) — small pruned ops (q, scores)
// ---------------------------------------------------------------------------
template <bool RELU>
__global__ __launch_bounds__(256) void sgemm_nt(
    const float* __restrict__ A, const float* __restrict__ W,
    const float* __restrict__ bias, float* __restrict__ C,
    int K, int lda, int ldw, int ldc, float alpha)
{
    __shared__ float As[8][128];
    __shared__ float Ws[8][128];

    const int tid = threadIdx.x;
    const int bm = blockIdx.y, bn = blockIdx.x;
    const int tx = tid & 15;
    const int ty = tid >> 4;
    const int lr = tid >> 1;
    const int lc = (tid & 1) << 2;

    const float* Ab = A + (size_t)(bm * 128 + lr) * lda + lc;
    const float* Wb = W + (size_t)(bn * 128 + lr) * ldw + lc;

    float acc[8][8];
#pragma unroll
    for (int i = 0; i < 8; i++)
#pragma unroll
        for (int j = 0; j < 8; j++) acc[i][j] = 0.0f;

    for (int k0 = 0; k0 < K; k0 += 8) {
        float4 av = *(const float4*)(Ab + k0);
        float4 wv = *(const float4*)(Wb + k0);
        As[lc + 0][lr] = av.x; As[lc + 1][lr] = av.y;
        As[lc + 2][lr] = av.z; As[lc + 3][lr] = av.w;
        Ws[lc + 0][lr] = wv.x; Ws[lc + 1][lr] = wv.y;
        Ws[lc + 2][lr] = wv.z; Ws[lc + 3][lr] = wv.w;
        __syncthreads();

#pragma unroll
        for (int kk = 0; kk < 8; kk++) {
            float a[8], b[8];
            *(float4*)(a)     = *(const float4*)&As[kk][ty * 8];
            *(float4*)(a + 4) = *(const float4*)&As[kk][ty * 8 + 4];
            *(float4*)(b)     = *(const float4*)&Ws[kk][tx * 8];
            *(float4*)(b + 4) = *(const float4*)&Ws[kk][tx * 8 + 4];
#pragma unroll
            for (int i = 0; i < 8; i++)
#pragma unroll
                for (int j = 0; j < 8; j++)
                    acc[i][j] = fmaf(a[i], b[j], acc[i][j]);
        }
        __syncthreads();
    }

#pragma unroll
    for (int i = 0; i < 8; i++) {
        const int row = bm * 128 + ty * 8 + i;
#pragma unroll
        for (int j = 0; j < 8; j++) {
            const int col = bn * 128 + tx * 8 + j;
            float v = acc[i][j] * alpha;
            if (bias) v += __ldg(&bias[col]);
            if (RELU) v = fmaxf(v, 0.0f);
            C[(size_t)row * ldc + col] = v;
        }
    }
}

// ---------------------------------------------------------------------------
__global__ void matvec_warp(const float* __restrict__ x, const float* __restrict__ W,
                            const float* __restrict__ b, float* __restrict__ y,
                            int N, int K, int relu)
{
    const int g = blockIdx.x * (blockDim.x >> 5) + (threadIdx.x >> 5);
    const int lane = threadIdx.x & 31;
    if (g >= N) return;
    const float* wr = W + (size_t)g * K;
    float s = 0.0f;
    for (int k = lane; k < K; k += 32) s = fmaf(x[k], wr[k], s);
#pragma unroll
    for (int o = 16; o; o >>= 1) s += __shfl_down_sync(0xffffffffu, s, o);
    if (lane == 0) {
        if (b) s += b[g];
        if (relu) s = fmaxf(s, 0.0f);
        y[g] = s;
    }
}

__global__ void vcol_kernel(const float* __restrict__ h, const float* __restrict__ wrow,
                            const float* __restrict__ brow, float* __restrict__ vcol)
{
    const int g = blockIdx.x * (blockDim.x >> 5) + (threadIdx.x >> 5);
    const int lane = threadIdx.x & 31;
    if (g >= 4096) return;
    const float* hr = h + (size_t)g * 512;
    float s = 0.0f;
    for (int k = lane; k < 512; k += 32) s = fmaf(hr[k], wrow[k], s);
#pragma unroll
    for (int o = 16; o; o >>= 1) s += __shfl_down_sync(0xffffffffu, s, o);
    if (lane == 0) vcol[g] = s + *brow;
}

__device__ __forceinline__ float blk_reduce(float v, float* red, bool ismax)
{
    const int tid = threadIdx.x;
    red[tid] = v;
    __syncthreads();
    for (int o = 128; o; o >>= 1) {
        if (tid < o) red[tid] = ismax ? fmaxf(red[tid], red[tid + o]) : (red[tid] + red[tid + o]);
        __syncthreads();
    }
    const float r = red[0];
    __syncthreads();
    return r;
}

__global__ __launch_bounds__(256) void attn_row(
    const float* __restrict__ s1, const float* __restrict__ s2,
    const float* __restrict__ vcol, const float* __restrict__ lamp,
    float* __restrict__ acol)
{
    __shared__ float red[256];
    const int r = blockIdx.x;
    const int tid = threadIdx.x;
    const int R = 3584 + r;
    const float* r1 = s1 + (size_t)r * 4096;
    const float* r2 = s2 + (size_t)r * 4096;

    float m1 = -1e30f, m2 = -1e30f;
    for (int s = tid; s < 4096; s += 256) {
        m1 = fmaxf(m1, r1[s]);
        m2 = fmaxf(m2, r2[s]);
    }
    m1 = blk_reduce(m1, red, true);
    m2 = blk_reduce(m2, red, true);

    float e1 = 0.f, w1 = 0.f, e2 = 0.f, w2 = 0.f, suf = 0.f;
    for (int s = tid; s < 4096; s += 256) {
        const float v = vcol[s];
        const float a = expf(r1[s] - m1);
        const float b = expf(r2[s] - m2);
        e1 += a; w1 = fmaf(a, v, w1);
        e2 += b; w2 = fmaf(b, v, w2);
        if (s > R) suf += v;
    }
    e1 = blk_reduce(e1, red, false);
    w1 = blk_reduce(w1, red, false);
    e2 = blk_reduce(e2, red, false);
    w2 = blk_reduce(w2, red, false);
    suf = blk_reduce(suf, red, false);

    if (tid == 0) acol[r] = w1 / e1 - (*lamp) * (w2 / e2) + suf;
}

__global__ void softmax_out(const float* __restrict__ logits, float* __restrict__ out)
{
    __shared__ float red[256];
    const int tid = threadIdx.x;
    const float v = logits[tid];
    const float m = blk_reduce(v, red, true);
    const float e = expf(v - m);
    const float s = blk_reduce(e, red, false);
    out[tid] = e / s;
}

// ---------------------------------------------------------------------------
extern "C" void kernel_launch(void* const* d_in, const int* in_sizes, int n_in,
                              void* d_out, int out_size)
{
    const float* x          = (const float*)d_in[0];
    const float* enc_w1     = (const float*)d_in[1];
    const float* enc_b1     = (const float*)d_in[2];
    const float* enc_w2     = (const float*)d_in[3];
    const float* enc_b2     = (const float*)d_in[4];
    const float* enc_w3     = (const float*)d_in[5];
    const float* enc_b3     = (const float*)d_in[6];
    const float* enc_w4     = (const float*)d_in[7];
    const float* enc_b4     = (const float*)d_in[8];
    const float* in_proj_w  = (const float*)d_in[9];
    const float* in_proj_b  = (const float*)d_in[10];
    const float* out_proj_w = (const float*)d_in[11];
    const float* out_proj_b = (const float*)d_in[12];
    const float* lam        = (const float*)d_in[13];
    const float* act_w1     = (const float*)d_in[14];
    const float* act_b1     = (const float*)d_in[15];
    const float* act_w2     = (const float*)d_in[16];
    const float* act_b2     = (const float*)d_in[17];
    const float* act_w3     = (const float*)d_in[18];
    const float* act_b3     = (const float*)d_in[19];

    __nv_bfloat16 *xhi, *xlo, *w1hi, *w1lo, *w2hi, *w2lo, *w3hi, *w3lo, *w4hi, *w4lo;
    __nv_bfloat16 *h1hi, *h1lo, *h2hi, *h2lo, *h3hi, *h3lo, *hhi, *hlo, *wkhi, *wklo;
    float *h, *k, *q, *s1, *s2, *vcol, *acol, *o, *m1, *m2, *lg;
    cudaGetSymbolAddress((void**)&xhi, g_xhi);   cudaGetSymbolAddress((void**)&xlo, g_xlo);
    cudaGetSymbolAddress((void**)&w1hi, g_w1hi); cudaGetSymbolAddress((void**)&w1lo, g_w1lo);
    cudaGetSymbolAddress((void**)&w2hi, g_w2hi); cudaGetSymbolAddress((void**)&w2lo, g_w2lo);
    cudaGetSymbolAddress((void**)&w3hi, g_w3hi); cudaGetSymbolAddress((void**)&w3lo, g_w3lo);
    cudaGetSymbolAddress((void**)&w4hi, g_w4hi); cudaGetSymbolAddress((void**)&w4lo, g_w4lo);
    cudaGetSymbolAddress((void**)&h1hi, g_h1hi); cudaGetSymbolAddress((void**)&h1lo, g_h1lo);
    cudaGetSymbolAddress((void**)&h2hi, g_h2hi); cudaGetSymbolAddress((void**)&h2lo, g_h2lo);
    cudaGetSymbolAddress((void**)&h3hi, g_h3hi); cudaGetSymbolAddress((void**)&h3lo, g_h3lo);
    cudaGetSymbolAddress((void**)&hhi, g_hhi);   cudaGetSymbolAddress((void**)&hlo, g_hlo);
    cudaGetSymbolAddress((void**)&wkhi, g_wkhi); cudaGetSymbolAddress((void**)&wklo, g_wklo);
    cudaGetSymbolAddress((void**)&h, g_h);
    cudaGetSymbolAddress((void**)&k, g_k);
    cudaGetSymbolAddress((void**)&q, g_q);
    cudaGetSymbolAddress((void**)&s1, g_s1);
    cudaGetSymbolAddress((void**)&s2, g_s2);
    cudaGetSymbolAddress((void**)&vcol, g_vcol);
    cudaGetSymbolAddress((void**)&acol, g_acol);
    cudaGetSymbolAddress((void**)&o, g_o);
    cudaGetSymbolAddress((void**)&m1, g_m1);
    cudaGetSymbolAddress((void**)&m2, g_m2);
    cudaGetSymbolAddress((void**)&lg, g_logits);

    const int SMEM_MMA = 2 * 40960;  // 81920 B dynamic smem
    cudaFuncSetAttribute(mma_gemm<0>, cudaFuncAttributeMaxDynamicSharedMemorySize, SMEM_MMA);
    cudaFuncSetAttribute(mma_gemm<1>, cudaFuncAttributeMaxDynamicSharedMemorySize, SMEM_MMA);
    cudaFuncSetAttribute(mma_gemm<2>, cudaFuncAttributeMaxDynamicSharedMemorySize, SMEM_MMA);

    // ---- bf16 splits of x, encoder weights, and k-projection weights ----
    split_f32<<<4096 * 1024 / 1024, 256>>>(x, xhi, xlo, 4096 * 1024);
    split_f32<<<2048 * 1024 / 1024, 256>>>(enc_w1, w1hi, w1lo, 2048 * 1024);
    split_f32<<<4096 * 2048 / 1024, 256>>>(enc_w2, w2hi, w2lo, 4096 * 2048);
    split_f32<<<2048 * 4096 / 1024, 256>>>(enc_w3, w3hi, w3lo, 2048 * 4096);
    split_f32<<<512 * 2048 / 1024, 256>>>(enc_w4, w4hi, w4lo, 512 * 2048);
    split_f32<<<512 * 512 / 1024, 256>>>(in_proj_w + (size_t)512 * 512, wkhi, wklo, 512 * 512);

    // ---- encoder on tensor cores ----
    mma_gemm<0><<<dim3(16, 32), 128, SMEM_MMA>>>(xhi, xlo, w1hi, w1lo, enc_b1,
                                                 h1hi, h1lo, nullptr, 1024, 2048);
    mma_gemm<0><<<dim3(32, 32), 128, SMEM_MMA>>>(h1hi, h1lo, w2hi, w2lo, enc_b2,
                                                 h2hi, h2lo, nullptr, 2048, 4096);
    mma_gemm<0><<<dim3(16, 32), 128, SMEM_MMA>>>(h2hi, h2lo, w3hi, w3lo, enc_b3,
                                                 h3hi, h3lo, nullptr, 4096, 2048);
    // h = h3 @ w4^T + b4 + PE: fp32 h AND bf16 split (for k on tensor path)
    mma_gemm<1><<<dim3(4, 32), 128, SMEM_MMA>>>(h3hi, h3lo, w4hi, w4lo, enc_b4,
                                                hhi, hlo, h, 2048, 512);
    // k = h @ Wk^T + bk: fp32 out (tensor path)
    mma_gemm<2><<<dim3(4, 32), 128, SMEM_MMA>>>(hhi, hlo, wkhi, wklo, in_proj_b + 512,
                                                nullptr, nullptr, k, 512, 512);

    // ---- pruned q + v column (scalar) ----
    sgemm_nt<false><<<dim3(4, 4), 256>>>(h + (size_t)3584 * 512, in_proj_w,
                                         in_proj_b, q, 512, 512, 512, 512, 1.0f);
    vcol_kernel<<<512, 256>>>(h, in_proj_w + (size_t)1535 * 512, in_proj_b + 1535, vcol);

    // ---- attention scores (rows 3584:4096) ----
    const float scale = 0.7071067811865475f;
    sgemm_nt<false><<<dim3(32, 4), 256>>>(q,       k,       nullptr, s1, 256, 512, 512, 4096, scale);
    sgemm_nt<false><<<dim3(32, 4), 256>>>(q + 256, k + 256, nullptr, s2, 256, 512, 512, 4096, scale);

    attn_row<<<512, 256>>>(s1, s2, vcol, lam, acol);

    // ---- final-row MLP ----
    matvec_warp<<<64, 256>>>(acol, out_proj_w, out_proj_b, o, 512, 512, 0);
    matvec_warp<<<128, 256>>>(o, act_w1, act_b1, m1, 1024, 512, 1);
    matvec_warp<<<256, 256>>>(m1, act_w2, act_b2, m2, 2048, 1024, 1);
    matvec_warp<<<32, 256>>>(m2, act_w3, act_b3, lg, 256, 2048, 0);

    softmax_out<<<1, 256>>>(lg, (float*)d_out);
}

// round 10
// speedup vs baseline: 2.2960x; 1.0049x over previous
#include <cuda_runtime.h>
#include <cuda_bf16.h>
#include <math.h>
#include <stdint.h>

// ===========================================================================
// S=4096, D_IN=1024, E=512, OUT=256, HEAD_DIM=2
// Output = softmax(row 4095 of post-attn MLP) -> pruned attention tail.
// Encoder GEMMs + k-projection on tensor cores via mma.sync bf16
// (compute_103-safe), 3-term split: C = Ahi*Bhi + Ahi*Blo + Alo*Bhi.
// R9/R10: inner loop restructured into 3 independent passes (hh/hl/lh) so each
// accumulator's reuse distance is 32 HMMAs (was 2) -> hide HMMA latency.
// ===========================================================================

// ---------------- scratch (__device__ globals; no cudaMalloc) --------------
__device__ __nv_bfloat16 g_xhi[4096*1024], g_xlo[4096*1024];
__device__ __nv_bfloat16 g_w1hi[2048*1024], g_w1lo[2048*1024];
__device__ __nv_bfloat16 g_w2hi[4096*2048], g_w2lo[4096*2048];
__device__ __nv_bfloat16 g_w3hi[2048*4096], g_w3lo[2048*4096];
__device__ __nv_bfloat16 g_w4hi[512*2048],  g_w4lo[512*2048];
__device__ __nv_bfloat16 g_h1hi[4096*2048], g_h1lo[4096*2048];
__device__ __nv_bfloat16 g_h2hi[4096*4096], g_h2lo[4096*4096];
__device__ __nv_bfloat16 g_h3hi[4096*2048], g_h3lo[4096*2048];
__device__ __nv_bfloat16 g_hhi[4096*512],   g_hlo[4096*512];
__device__ __nv_bfloat16 g_wkhi[512*512],   g_wklo[512*512];

__device__ float g_h[4096 * 512];
__device__ float g_k[4096 * 512];
__device__ float g_q[512 * 512];
__device__ float g_s1[512 * 4096];
__device__ float g_s2[512 * 4096];
__device__ float g_vcol[4096];
__device__ float g_acol[512];
__device__ float g_o[512];
__device__ float g_m1[1024];
__device__ float g_m2[2048];
__device__ float g_logits[256];

// ---------------- PTX helpers ----------------------------------------------
__device__ __forceinline__ uint32_t smem_u32(const void* p) {
    uint32_t a;
    asm("{ .reg .u64 t; cvta.to.shared.u64 t, %1; cvt.u32.u64 %0, t; }" : "=r"(a) : "l"(p));
    return a;
}

#define CP_ASYNC16(dst, src) \
    asm volatile("cp.async.cg.shared.global [%0], [%1], 16;\n" :: "r"(dst), "l"(src))
#define CP_COMMIT() asm volatile("cp.async.commit_group;\n" ::: "memory")
#define CP_WAIT(n)  asm volatile("cp.async.wait_group %0;\n" :: "n"(n) : "memory")

__device__ __forceinline__ void ldm_x4(uint32_t* r, uint32_t addr) {
    asm volatile("ldmatrix.sync.aligned.m8n8.x4.shared.b16 {%0,%1,%2,%3}, [%4];"
                 : "=r"(r[0]), "=r"(r[1]), "=r"(r[2]), "=r"(r[3]) : "r"(addr));
}

__device__ __forceinline__ void mma_bf16(float* c, const uint32_t* a, uint32_t b0, uint32_t b1) {
    asm volatile(
        "mma.sync.aligned.m16n8k16.row.col.f32.bf16.bf16.f32 "
        "{%0,%1,%2,%3}, {%4,%5,%6,%7}, {%8,%9}, {%0,%1,%2,%3};"
        : "+f"(c[0]), "+f"(c[1]), "+f"(c[2]), "+f"(c[3])
        : "r"(a[0]), "r"(a[1]), "r"(a[2]), "r"(a[3]), "r"(b0), "r"(b1));
}

__device__ __forceinline__ uint32_t pack_bf2(float v0, float v1) {
    __nv_bfloat16 h0 = __float2bfloat16(v0), h1 = __float2bfloat16(v1);
    return (uint32_t)__bfloat16_as_ushort(h0) | ((uint32_t)__bfloat16_as_ushort(h1) << 16);
}

// ---------------------------------------------------------------------------
__global__ void split_f32(const float* __restrict__ in, __nv_bfloat16* __restrict__ hi,
                          __nv_bfloat16* __restrict__ lo, int n)
{
    int i = (blockIdx.x * blockDim.x + threadIdx.x) * 4;
    if (i >= n) return;
    float4 v = *(const float4*)(in + i);
    __nv_bfloat16 h0 = __float2bfloat16(v.x), h1 = __float2bfloat16(v.y);
    __nv_bfloat16 h2 = __float2bfloat16(v.z), h3 = __float2bfloat16(v.w);
    uint32_t hp0 = pack_bf2(v.x, v.y), hp1 = pack_bf2(v.z, v.w);
    uint32_t lp0 = pack_bf2(v.x - __bfloat162float(h0), v.y - __bfloat162float(h1));
    uint32_t lp1 = pack_bf2(v.z - __bfloat162float(h2), v.w - __bfloat162float(h3));
    *(uint2*)(hi + i) = make_uint2(hp0, hp1);
    *(uint2*)(lo + i) = make_uint2(lp0, lp1);
}

// ---------------------------------------------------------------------------
// mma.sync bf16 split-GEMM. C[M,N] = sum_k A[m,k]*B[n,k] (3-term split).
// CTA: 128x128, BK=32, 128 threads = 4 warps in 2x2, each warp 64x64.
// Inner K16-step: preload ALL fragments (ah,al,bh,bl), then 3 passes of 32
// independent HMMAs (hh, hl, lh) -> acc reuse distance 32 hides HMMA latency.
// EPI=0: relu(acc+bias)        -> bf16 hi/lo
// EPI=1: acc+bias+PE           -> fp32 AND bf16 hi/lo
// EPI=2: acc+bias              -> fp32
// smem/stage: 4 tiles (Ahi,Alo,Bhi,Blo) x 128 rows x 80B = 40960B.
// ---------------------------------------------------------------------------
template <int EPI>
__global__ __launch_bounds__(128) void mma_gemm(
    const __nv_bfloat16* __restrict__ Ahi, const __nv_bfloat16* __restrict__ Alo,
    const __nv_bfloat16* __restrict__ Bhi, const __nv_bfloat16* __restrict__ Blo,
    const float* __restrict__ bias,
    __nv_bfloat16* __restrict__ Chi, __nv_bfloat16* __restrict__ Clo,
    float* __restrict__ Cf, int K, int N)
{
    extern __shared__ char smem[];
    const uint32_t sb = smem_u32(smem);
    const int tid = threadIdx.x;
    const int wid = tid >> 5;
    const int lane = tid & 31;
    const int warp_m = wid >> 1;      // 0..1 -> 64 rows
    const int warp_n = wid & 1;       // 0..1 -> 64 cols
    const int bm = blockIdx.y, bn = blockIdx.x;

    const __nv_bfloat16* gptr[4] = {
        Ahi + (size_t)bm * 128 * K, Alo + (size_t)bm * 128 * K,
        Bhi + (size_t)bn * 128 * K, Blo + (size_t)bn * 128 * K };

    auto load_tile = [&](int s, int k0) {
#pragma unroll
        for (int i = 0; i < 16; i++) {
            int idx = tid + i * 128;          // 0..2047 chunks of 16B
            int t   = idx >> 9;               // tensor 0..3
            int row = (idx >> 2) & 127;
            int c   = idx & 3;
            uint32_t dst = sb + s * 40960 + t * 10240 + row * 80 + c * 16;
            CP_ASYNC16(dst, gptr[t] + (size_t)row * K + k0 + c * 8);
        }
    };

    float acc[4][8][4];
#pragma unroll
    for (int i = 0; i < 4; i++)
#pragma unroll
        for (int j = 0; j < 8; j++)
#pragma unroll
            for (int l = 0; l < 4; l++) acc[i][j][l] = 0.0f;

    const int T = K >> 5;
    load_tile(0, 0);
    CP_COMMIT();

    for (int t = 0; t < T; t++) {
        const int buf = t & 1;
        if (t + 1 < T) { load_tile(buf ^ 1, (t + 1) << 5); CP_COMMIT(); CP_WAIT(1); }
        else           { CP_WAIT(0); }
        __syncthreads();

        const uint32_t sa = sb + buf * 40960;
#pragma unroll
        for (int ks = 0; ks < 2; ks++) {
            const int kb = ks * 32 + ((lane >= 16) ? 16 : 0);
            const int lr = lane & 15;

            // ---- preload ALL fragments for this K16 step ----
            uint32_t ah[4][4], al[4][4], bh[4][4], bl[4][4];
#pragma unroll
            for (int mf = 0; mf < 4; mf++) {
                uint32_t addr = sa + (uint32_t)(warp_m * 64 + mf * 16 + lr) * 80 + kb;
                ldm_x4(ah[mf], addr);
                ldm_x4(al[mf], addr + 10240);
            }
#pragma unroll
            for (int bt = 0; bt < 4; bt++) {
                uint32_t addr = sa + 20480 + (uint32_t)(warp_n * 64 + bt * 16 + lr) * 80 + kb;
                ldm_x4(bh[bt], addr);
                ldm_x4(bl[bt], addr + 10240);
            }

            // ---- pass 1: Ahi * Bhi (32 independent HMMAs) ----
#pragma unroll
            for (int bt = 0; bt < 4; bt++)
#pragma unroll
                for (int mf = 0; mf < 4; mf++) {
                    mma_bf16(acc[mf][2 * bt],     ah[mf], bh[bt][0], bh[bt][2]);
                    mma_bf16(acc[mf][2 * bt + 1], ah[mf], bh[bt][1], bh[bt][3]);
                }
            // ---- pass 2: Ahi * Blo ----
#pragma unroll
            for (int bt = 0; bt < 4; bt++)
#pragma unroll
                for (int mf = 0; mf < 4; mf++) {
                    mma_bf16(acc[mf][2 * bt],     ah[mf], bl[bt][0], bl[bt][2]);
                    mma_bf16(acc[mf][2 * bt + 1], ah[mf], bl[bt][1], bl[bt][3]);
                }
            // ---- pass 3: Alo * Bhi ----
#pragma unroll
            for (int bt = 0; bt < 4; bt++)
#pragma unroll
                for (int mf = 0; mf < 4; mf++) {
                    mma_bf16(acc[mf][2 * bt],     al[mf], bh[bt][0], bh[bt][2]);
                    mma_bf16(acc[mf][2 * bt + 1], al[mf], bh[bt][1], bh[bt][3]);
                }
        }
        __syncthreads();
    }

    // ---- epilogue ----
    const int rbase = bm * 128 + warp_m * 64 + (lane >> 2);
    const int cbase = bn * 128 + warp_n * 64 + (lane & 3) * 2;
#pragma unroll
    for (int mf = 0; mf < 4; mf++) {
#pragma unroll
        for (int nf = 0; nf < 8; nf++) {
            const int c0 = cbase + nf * 8;          // even column
            const float b0 = __ldg(&bias[c0]), b1 = __ldg(&bias[c0 + 1]);
#pragma unroll
            for (int rr = 0; rr < 2; rr++) {
                const int row = rbase + mf * 16 + rr * 8;
                float v0 = acc[mf][nf][rr * 2]     + b0;
                float v1 = acc[mf][nf][rr * 2 + 1] + b1;
                if (EPI == 1) {
                    const float dv = expf(-(float)c0 * (9.210340371976184f / 512.0f));
                    const float arg = (float)row * dv;
                    v0 += sinf(arg);
                    v1 += cosf(arg);
                }
                if (EPI == 0) {
                    v0 = fmaxf(v0, 0.0f); v1 = fmaxf(v1, 0.0f);
                }
                if (EPI == 0 || EPI == 1) {
                    __nv_bfloat16 h0 = __float2bfloat16(v0), h1 = __float2bfloat16(v1);
                    float l0 = v0 - __bfloat162float(h0), l1 = v1 - __bfloat162float(h1);
                    *(uint32_t*)(Chi + (size_t)row * N + c0) =
                        (uint32_t)__bfloat16_as_ushort(h0) |
                        ((uint32_t)__bfloat16_as_ushort(h1) << 16);
                    *(uint32_t*)(Clo + (size_t)row * N + c0) = pack_bf2(l0, l1);
                }
                if (EPI == 1 || EPI == 2) {
                    *(float2*)(Cf + (size_t)row * N + c0) = make_float2(v0, v1);
                }
            }
        }
    }
}

// ---------------------------------------------------------------------------
// Scalar SGEMM (NT) — small pruned ops (q, scores)
// ---------------------------------------------------------------------------
template <bool RELU>
__global__ __launch_bounds__(256) void sgemm_nt(
    const float* __restrict__ A, const float* __restrict__ W,
    const float* __restrict__ bias, float* __restrict__ C,
    int K, int lda, int ldw, int ldc, float alpha)
{
    __shared__ float As[8][128];
    __shared__ float Ws[8][128];

    const int tid = threadIdx.x;
    const int bm = blockIdx.y, bn = blockIdx.x;
    const int tx = tid & 15;
    const int ty = tid >> 4;
    const int lr = tid >> 1;
    const int lc = (tid & 1) << 2;

    const float* Ab = A + (size_t)(bm * 128 + lr) * lda + lc;
    const float* Wb = W + (size_t)(bn * 128 + lr) * ldw + lc;

    float acc[8][8];
#pragma unroll
    for (int i = 0; i < 8; i++)
#pragma unroll
        for (int j = 0; j < 8; j++) acc[i][j] = 0.0f;

    for (int k0 = 0; k0 < K; k0 += 8) {
        float4 av = *(const float4*)(Ab + k0);
        float4 wv = *(const float4*)(Wb + k0);
        As[lc + 0][lr] = av.x; As[lc + 1][lr] = av.y;
        As[lc + 2][lr] = av.z; As[lc + 3][lr] = av.w;
        Ws[lc + 0][lr] = wv.x; Ws[lc + 1][lr] = wv.y;
        Ws[lc + 2][lr] = wv.z; Ws[lc + 3][lr] = wv.w;
        __syncthreads();

#pragma unroll
        for (int kk = 0; kk < 8; kk++) {
            float a[8], b[8];
            *(float4*)(a)     = *(const float4*)&As[kk][ty * 8];
            *(float4*)(a + 4) = *(const float4*)&As[kk][ty * 8 + 4];
            *(float4*)(b)     = *(const float4*)&Ws[kk][tx * 8];
            *(float4*)(b + 4) = *(const float4*)&Ws[kk][tx * 8 + 4];
#pragma unroll
            for (int i = 0; i < 8; i++)
#pragma unroll
                for (int j = 0; j < 8; j++)
                    acc[i][j] = fmaf(a[i], b[j], acc[i][j]);
        }
        __syncthreads();
    }

#pragma unroll
    for (int i = 0; i < 8; i++) {
        const int row = bm * 128 + ty * 8 + i;
#pragma unroll
        for (int j = 0; j < 8; j++) {
            const int col = bn * 128 + tx * 8 + j;
            float v = acc[i][j] * alpha;
            if (bias) v += __ldg(&bias[col]);
            if (RELU) v = fmaxf(v, 0.0f);
            C[(size_t)row * ldc + col] = v;
        }
    }
}

// ---------------------------------------------------------------------------
__global__ void matvec_warp(const float* __restrict__ x, const float* __restrict__ W,
                            const float* __restrict__ b, float* __restrict__ y,
                            int N, int K, int relu)
{
    const int g = blockIdx.x * (blockDim.x >> 5) + (threadIdx.x >> 5);
    const int lane = threadIdx.x & 31;
    if (g >= N) return;
    const float* wr = W + (size_t)g * K;
    float s = 0.0f;
    for (int k = lane; k < K; k += 32) s = fmaf(x[k], wr[k], s);
#pragma unroll
    for (int o = 16; o; o >>= 1) s += __shfl_down_sync(0xffffffffu, s, o);
    if (lane == 0) {
        if (b) s += b[g];
        if (relu) s = fmaxf(s, 0.0f);
        y[g] = s;
    }
}

__global__ void vcol_kernel(const float* __restrict__ h, const float* __restrict__ wrow,
                            const float* __restrict__ brow, float* __restrict__ vcol)
{
    const int g = blockIdx.x * (blockDim.x >> 5) + (threadIdx.x >> 5);
    const int lane = threadIdx.x & 31;
    if (g >= 4096) return;
    const float* hr = h + (size_t)g * 512;
    float s = 0.0f;
    for (int k = lane; k < 512; k += 32) s = fmaf(hr[k], wrow[k], s);
#pragma unroll
    for (int o = 16; o; o >>= 1) s += __shfl_down_sync(0xffffffffu, s, o);
    if (lane == 0) vcol[g] = s + *brow;
}

__device__ __forceinline__ float blk_reduce(float v, float* red, bool ismax)
{
    const int tid = threadIdx.x;
    red[tid] = v;
    __syncthreads();
    for (int o = 128; o; o >>= 1) {
        if (tid < o) red[tid] = ismax ? fmaxf(red[tid], red[tid + o]) : (red[tid] + red[tid + o]);
        __syncthreads();
    }
    const float r = red[0];
    __syncthreads();
    return r;
}

__global__ __launch_bounds__(256) void attn_row(
    const float* __restrict__ s1, const float* __restrict__ s2,
    const float* __restrict__ vcol, const float* __restrict__ lamp,
    float* __restrict__ acol)
{
    __shared__ float red[256];
    const int r = blockIdx.x;
    const int tid = threadIdx.x;
    const int R = 3584 + r;
    const float* r1 = s1 + (size_t)r * 4096;
    const float* r2 = s2 + (size_t)r * 4096;

    float m1 = -1e30f, m2 = -1e30f;
    for (int s = tid; s < 4096; s += 256) {
        m1 = fmaxf(m1, r1[s]);
        m2 = fmaxf(m2, r2[s]);
    }
    m1 = blk_reduce(m1, red, true);
    m2 = blk_reduce(m2, red, true);

    float e1 = 0.f, w1 = 0.f, e2 = 0.f, w2 = 0.f, suf = 0.f;
    for (int s = tid; s < 4096; s += 256) {
        const float v = vcol[s];
        const float a = expf(r1[s] - m1);
        const float b = expf(r2[s] - m2);
        e1 += a; w1 = fmaf(a, v, w1);
        e2 += b; w2 = fmaf(b, v, w2);
        if (s > R) suf += v;
    }
    e1 = blk_reduce(e1, red, false);
    w1 = blk_reduce(w1, red, false);
    e2 = blk_reduce(e2, red, false);
    w2 = blk_reduce(w2, red, false);
    suf = blk_reduce(suf, red, false);

    if (tid == 0) acol[r] = w1 / e1 - (*lamp) * (w2 / e2) + suf;
}

__global__ void softmax_out(const float* __restrict__ logits, float* __restrict__ out)
{
    __shared__ float red[256];
    const int tid = threadIdx.x;
    const float v = logits[tid];
    const float m = blk_reduce(v, red, true);
    const float e = expf(v - m);
    const float s = blk_reduce(e, red, false);
    out[tid] = e / s;
}

// ---------------------------------------------------------------------------
extern "C" void kernel_launch(void* const* d_in, const int* in_sizes, int n_in,
                              void* d_out, int out_size)
{
    const float* x          = (const float*)d_in[0];
    const float* enc_w1     = (const float*)d_in[1];
    const float* enc_b1     = (const float*)d_in[2];
    const float* enc_w2     = (const float*)d_in[3];
    const float* enc_b2     = (const float*)d_in[4];
    const float* enc_w3     = (const float*)d_in[5];
    const float* enc_b3     = (const float*)d_in[6];
    const float* enc_w4     = (const float*)d_in[7];
    const float* enc_b4     = (const float*)d_in[8];
    const float* in_proj_w  = (const float*)d_in[9];
    const float* in_proj_b  = (const float*)d_in[10];
    const float* out_proj_w = (const float*)d_in[11];
    const float* out_proj_b = (const float*)d_in[12];
    const float* lam        = (const float*)d_in[13];
    const float* act_w1     = (const float*)d_in[14];
    const float* act_b1     = (const float*)d_in[15];
    const float* act_w2     = (const float*)d_in[16];
    const float* act_b2     = (const float*)d_in[17];
    const float* act_w3     = (const float*)d_in[18];
    const float* act_b3     = (const float*)d_in[19];

    __nv_bfloat16 *xhi, *xlo, *w1hi, *w1lo, *w2hi, *w2lo, *w3hi, *w3lo, *w4hi, *w4lo;
    __nv_bfloat16 *h1hi, *h1lo, *h2hi, *h2lo, *h3hi, *h3lo, *hhi, *hlo, *wkhi, *wklo;
    float *h, *k, *q, *s1, *s2, *vcol, *acol, *o, *m1, *m2, *lg;
    cudaGetSymbolAddress((void**)&xhi, g_xhi);   cudaGetSymbolAddress((void**)&xlo, g_xlo);
    cudaGetSymbolAddress((void**)&w1hi, g_w1hi); cudaGetSymbolAddress((void**)&w1lo, g_w1lo);
    cudaGetSymbolAddress((void**)&w2hi, g_w2hi); cudaGetSymbolAddress((void**)&w2lo, g_w2lo);
    cudaGetSymbolAddress((void**)&w3hi, g_w3hi); cudaGetSymbolAddress((void**)&w3lo, g_w3lo);
    cudaGetSymbolAddress((void**)&w4hi, g_w4hi); cudaGetSymbolAddress((void**)&w4lo, g_w4lo);
    cudaGetSymbolAddress((void**)&h1hi, g_h1hi); cudaGetSymbolAddress((void**)&h1lo, g_h1lo);
    cudaGetSymbolAddress((void**)&h2hi, g_h2hi); cudaGetSymbolAddress((void**)&h2lo, g_h2lo);
    cudaGetSymbolAddress((void**)&h3hi, g_h3hi); cudaGetSymbolAddress((void**)&h3lo, g_h3lo);
    cudaGetSymbolAddress((void**)&hhi, g_hhi);   cudaGetSymbolAddress((void**)&hlo, g_hlo);
    cudaGetSymbolAddress((void**)&wkhi, g_wkhi); cudaGetSymbolAddress((void**)&wklo, g_wklo);
    cudaGetSymbolAddress((void**)&h, g_h);
    cudaGetSymbolAddress((void**)&k, g_k);
    cudaGetSymbolAddress((void**)&q, g_q);
    cudaGetSymbolAddress((void**)&s1, g_s1);
    cudaGetSymbolAddress((void**)&s2, g_s2);
    cudaGetSymbolAddress((void**)&vcol, g_vcol);
    cudaGetSymbolAddress((void**)&acol, g_acol);
    cudaGetSymbolAddress((void**)&o, g_o);
    cudaGetSymbolAddress((void**)&m1, g_m1);
    cudaGetSymbolAddress((void**)&m2, g_m2);
    cudaGetSymbolAddress((void**)&lg, g_logits);

    const int SMEM_MMA = 2 * 40960;  // 81920 B dynamic smem
    cudaFuncSetAttribute(mma_gemm<0>, cudaFuncAttributeMaxDynamicSharedMemorySize, SMEM_MMA);
    cudaFuncSetAttribute(mma_gemm<1>, cudaFuncAttributeMaxDynamicSharedMemorySize, SMEM_MMA);
    cudaFuncSetAttribute(mma_gemm<2>, cudaFuncAttributeMaxDynamicSharedMemorySize, SMEM_MMA);

    // ---- splits + encoder, ordered so ncu (-s 5 -c 1) captures the h2 GEMM
    // launch order: 1 split_x, 2 split_w1, 3 split_w2, 4 gemm_h1, 5 split_w3,
    //               6 gemm_h2 (captured), ...
    split_f32<<<4096 * 1024 / 1024, 256>>>(x, xhi, xlo, 4096 * 1024);
    split_f32<<<2048 * 1024 / 1024, 256>>>(enc_w1, w1hi, w1lo, 2048 * 1024);
    split_f32<<<4096 * 2048 / 1024, 256>>>(enc_w2, w2hi, w2lo, 4096 * 2048);

    // h1 = relu(x @ w1^T + b1): M=4096, N=2048, K=1024
    mma_gemm<0><<<dim3(16, 32), 128, SMEM_MMA>>>(xhi, xlo, w1hi, w1lo, enc_b1,
                                                 h1hi, h1lo, nullptr, 1024, 2048);
    split_f32<<<2048 * 4096 / 1024, 256>>>(enc_w3, w3hi, w3lo, 2048 * 4096);
    // h2 = relu(h1 @ w2^T + b2): N=4096, K=2048   <-- profiled launch
    mma_gemm<0><<<dim3(32, 32), 128, SMEM_MMA>>>(h1hi, h1lo, w2hi, w2lo, enc_b2,
                                                 h2hi, h2lo, nullptr, 2048, 4096);
    split_f32<<<512 * 2048 / 1024, 256>>>(enc_w4, w4hi, w4lo, 512 * 2048);
    split_f32<<<512 * 512 / 1024, 256>>>(in_proj_w + (size_t)512 * 512, wkhi, wklo, 512 * 512);
    // h3 = relu(h2 @ w3^T + b3): N=2048, K=4096
    mma_gemm<0><<<dim3(16, 32), 128, SMEM_MMA>>>(h2hi, h2lo, w3hi, w3lo, enc_b3,
                                                 h3hi, h3lo, nullptr, 4096, 2048);
    // h = h3 @ w4^T + b4 + PE: fp32 h AND bf16 split (for k on tensor path)
    mma_gemm<1><<<dim3(4, 32), 128, SMEM_MMA>>>(h3hi, h3lo, w4hi, w4lo, enc_b4,
                                                hhi, hlo, h, 2048, 512);
    // k = h @ Wk^T + bk: fp32 out (tensor path)
    mma_gemm<2><<<dim3(4, 32), 128, SMEM_MMA>>>(hhi, hlo, wkhi, wklo, in_proj_b + 512,
                                                nullptr, nullptr, k, 512, 512);

    // ---- pruned q + v column (scalar) ----
    sgemm_nt<false><<<dim3(4, 4), 256>>>(h + (size_t)3584 * 512, in_proj_w,
                                         in_proj_b, q, 512, 512, 512, 512, 1.0f);
    vcol_kernel<<<512, 256>>>(h, in_proj_w + (size_t)1535 * 512, in_proj_b + 1535, vcol);

    // ---- attention scores (rows 3584:4096) ----
    const float scale = 0.7071067811865475f;
    sgemm_nt<false><<<dim3(32, 4), 256>>>(q,       k,       nullptr, s1, 256, 512, 512, 4096, scale);
    sgemm_nt<false><<<dim3(32, 4), 256>>>(q + 256, k + 256, nullptr, s2, 256, 512, 512, 4096, scale);

    attn_row<<<512, 256>>>(s1, s2, vcol, lam, acol);

    // ---- final-row MLP ----
    matvec_warp<<<64, 256>>>(acol, out_proj_w, out_proj_b, o, 512, 512, 0);
    matvec_warp<<<128, 256>>>(o, act_w1, act_b1, m1, 1024, 512, 1);
    matvec_warp<<<256, 256>>>(m1, act_w2, act_b2, m2, 2048, 1024, 1);
    matvec_warp<<<32, 256>>>(m2, act_w3, act_b3, lg, 256, 2048, 0);

    softmax_out<<<1, 256>>>(lg, (float*)d_out);
}